// round 16
// baseline (speedup 1.0000x reference)
#include <cuda_runtime.h>
#include <stdint.h>

#define G_MEAN_F 85.384f
#define G_STD_F  53.798f

static __device__ __forceinline__ float warp_sum(float f) {
    #pragma unroll
    for (int o = 16; o; o >>= 1) f += __shfl_down_sync(0xffffffffu, f, o);
    return f;
}

// packed f32x2 helpers (sm_103a)
static __device__ __forceinline__ uint64_t pkf2(float lo, float hi) {
    uint64_t r; asm("mov.b64 %0, {%1, %2};" : "=l"(r) : "f"(lo), "f"(hi)); return r;
}
static __device__ __forceinline__ uint64_t add_f32x2(uint64_t a, uint64_t b) {
    uint64_t r; asm("add.rn.f32x2 %0, %1, %2;" : "=l"(r) : "l"(a), "l"(b)); return r;
}
static __device__ __forceinline__ uint64_t fma_f32x2(uint64_t a, uint64_t b, uint64_t c) {
    uint64_t r; asm("fma.rn.f32x2 %0, %1, %2, %3;" : "=l"(r) : "l"(a), "l"(b), "l"(c)); return r;
}
static __device__ __forceinline__ void upk2(uint64_t v, float& lo, float& hi) {
    asm("mov.b64 {%0, %1}, %2;" : "=f"(lo), "=f"(hi) : "l"(v));
}

// Per-offset parameters, built at compile time, stored in __constant__.
struct OffParams {
    uint32_t mask[10];  // 289-bit validity mask for 'a' positions (words 0..9)
    int      sh;        // K & 31  (K = dr*17+dc)
    int      tot;       // (17-dr)*(17-|dc|)
    float    invTot;    // 1 / (2*tot)
    int      slot1;     // output slot
    int      slot2;     // duplicate slot or -1
};

static constexpr OffParams make_op(int dr, int dc, int s1, int s2) {
    OffParams p{};
    const int adc = dc < 0 ? -dc : dc;
    for (int r = 0; r <= 16 - dr; ++r)
        for (int c = 0; c < 17; ++c) {
            bool ok = (dc >= 0) ? (c <= 16 - dc) : (c >= adc);
            if (ok) { int q = r * 17 + c; p.mask[q >> 5] |= (1u << (q & 31)); }
        }
    const int K = dr * 17 + dc;
    p.sh = K & 31;
    p.tot = (17 - dr) * (17 - adc);
    p.invTot = 1.0f / (2.0f * (float)p.tot);
    p.slot1 = s1;
    p.slot2 = s2;
    return p;
}

// Grouped by (word-offset WO, max nonzero mask word WMAX):
//  [0..2]  WO=0 WMAX=10 : (0,1) (0,2) (0,4)        [dr=0]
//  [3..5]  WO=0 WMAX=9  : (1,1) (1,-1) (1,0)       [dr=1]
//  [6..8]  WO=1 WMAX=8  : (2,0) (3,3) (3,-3)
//  [9]     WO=2 WMAX=7  : (4,0)
__constant__ OffParams OP[10] = {
    make_op(0, 1,  0, -1),
    make_op(0, 2,  4, -1),
    make_op(0, 4,  8, -1),
    make_op(1, 1,  1,  5),
    make_op(1,-1,  3,  7),
    make_op(1, 0,  2, -1),
    make_op(2, 0,  6, -1),
    make_op(3, 3,  9, -1),
    make_op(3,-3, 11, -1),
    make_op(4, 0, 10, -1),
};

// GLCM symmetric counting + features for one offset; WO compile-time (static reg
// indices into C), sh/mask/tot runtime from constant memory.
// Entropy uses smem LUT slut[s] = s*log2(s).
template<int WO, int WMAX>
__device__ __forceinline__ void do_off(const OffParams& op, const uint32_t C[4][12],
                                       const float* __restrict__ slut, float feat[5])
{
    const int sh = op.sh;

    int X12=0, X13=0, X14=0, X23=0, X24=0, X34=0;
    int D1=0, D2=0, D3=0, D4=0;
    int E1=0, E2=0, E3=0, E4=0;

    #pragma unroll
    for (int w = 0; w < WMAX; ++w) {
        const uint32_t mk = op.mask[w];
        const uint32_t a0 = C[0][w], a1 = C[1][w], a2 = C[2][w], a3 = C[3][w];
        const uint32_t s0 = __funnelshift_r(C[0][w+WO], C[0][w+WO+1], sh) & mk;
        const uint32_t s1 = __funnelshift_r(C[1][w+WO], C[1][w+WO+1], sh) & mk;
        const uint32_t s2 = __funnelshift_r(C[2][w+WO], C[2][w+WO+1], sh) & mk;
        const uint32_t s3 = __funnelshift_r(C[3][w+WO], C[3][w+WO+1], sh) & mk;

        E1 += __popc(a0 & mk) + __popc(s0);
        E2 += __popc(a1 & mk) + __popc(s1);
        E3 += __popc(a2 & mk) + __popc(s2);
        E4 += __popc(a3 & mk) + __popc(s3);

        D1 += __popc(a0 & s0);
        D2 += __popc(a1 & s1);
        D3 += __popc(a2 & s2);
        D4 += __popc(a3 & s3);

        X12 += __popc(a0 & s1) + __popc(a1 & s0);
        X13 += __popc(a0 & s2) + __popc(a2 & s0);
        X14 += __popc(a0 & s3) + __popc(a3 & s0);
        X23 += __popc(a1 & s2) + __popc(a2 & s1);
        X24 += __popc(a1 & s3) + __popc(a3 & s1);
        X34 += __popc(a2 & s3) + __popc(a3 & s2);
    }

    // symmetrized cells from symmetric cumulative scalars
    const int TOT = op.tot;
    const int U11 = 2*D1, U22 = 2*D2, U33 = 2*D3, U44 = 2*D4;
    const int s00 = 2*TOT - 2*E1 + U11;
    const int s01 = E1  - U11 - E2  + X12;
    const int s02 = E2  - X12 - E3  + X13;
    const int s03 = E3  - X13 - E4  + X14;
    const int s04 = E4  - X14;
    const int s11 = U11 - 2*X12 + U22;
    const int s12 = X12 - U22 - X13 + X23;
    const int s13 = X13 - X23 - X14 + X24;
    const int s14 = X14 - X24;
    const int s22 = U22 - 2*X23 + U33;
    const int s23 = X23 - U33 - X24 + X34;
    const int s24 = X24 - X34;
    const int s33 = U33 - 2*X34 + U44;
    const int s34 = X34 - U44;
    const int s44 = U44;

    const float invTot = op.invTot;

    // contrast
    {
        int ci = (s01 + s12 + s23 + s34) + 4*(s02 + s13 + s24) + 9*(s03 + s14) + 16*s04;
        feat[0] = 2.0f * invTot * (float)ci;
    }
    // homogeneity
    {
        float hoU = 0.5f*(float)(s01+s12+s23+s34)
                  + 0.2f*(float)(s02+s13+s24)
                  + 0.1f*(float)(s03+s14)
                  + (1.0f/17.0f)*(float)s04;
        feat[1] = invTot * ((float)(s00+s11+s22+s33+s44) + 2.0f*hoU);
    }
    // energy
    {
        int e2i = s00*s00 + s11*s11 + s22*s22 + s33*s33 + s44*s44
                + 2*(s01*s01 + s02*s02 + s03*s03 + s04*s04
                   + s12*s12 + s13*s13 + s14*s14
                   + s23*s23 + s24*s24 + s34*s34);
        feat[2] = invTot * sqrtf((float)e2i);
    }
    // correlation
    {
        int t1 = s01+s11+s12+s13+s14;
        int t2 = s02+s12+s22+s23+s24;
        int t3 = s03+s13+s23+s33+s34;
        int t4 = s04+s14+s24+s34+s44;
        float mu  = invTot * (float)(t1 + 2*t2 + 3*t3 + 4*t4);
        float e2m = invTot * (float)(t1 + 4*t2 + 9*t3 + 16*t4);
        float varm = e2m - mu * mu;
        int wij = s11 + 4*s22 + 9*s33 + 16*s44
                + 2*(2*s12 + 3*s13 + 4*s14 + 6*s23 + 8*s24 + 12*s34);
        float cov = invTot * (float)wij - mu * mu;
        feat[3] = (varm < 1e-15f) ? 1.0f : __fdividef(cov, fmaxf(varm, 1e-30f));
    }
    // entropy via LUT: slut[s] = s*log2(s); diag x1, off-diag x2
    {
        float S1 = slut[s00] + slut[s11] + slut[s22] + slut[s33] + slut[s44];
        float S2 = slut[s01] + slut[s02] + slut[s03] + slut[s04]
                 + slut[s12] + slut[s13] + slut[s14]
                 + slut[s23] + slut[s24] + slut[s34];
        feat[4] = -fmaf(invTot, fmaf(2.0f, S2, S1), __log2f(invTot));
    }
}

static __device__ __forceinline__ void emit_feats(const OffParams& op, const float feat[5],
                                                  float valid, float* sacc, bool lane0)
{
    const int sl1 = op.slot1;
    const int sl2 = op.slot2;
    float f;
    f = warp_sum(feat[0] * valid);
    if (lane0) { atomicAdd(&sacc[ 8+sl1], f); if (sl2 >= 0) atomicAdd(&sacc[ 8+sl2], f); }
    f = warp_sum(feat[1] * valid);
    if (lane0) { atomicAdd(&sacc[20+sl1], f); if (sl2 >= 0) atomicAdd(&sacc[20+sl2], f); }
    f = warp_sum(feat[2] * valid);
    if (lane0) { atomicAdd(&sacc[32+sl1], f); if (sl2 >= 0) atomicAdd(&sacc[32+sl2], f); }
    f = warp_sum(feat[3] * valid);
    if (lane0) { atomicAdd(&sacc[44+sl1], f); if (sl2 >= 0) atomicAdd(&sacc[44+sl2], f); }
    f = warp_sum(feat[4] * valid);
    if (lane0) { atomicAdd(&sacc[56+sl1], f); if (sl2 >= 0) atomicAdd(&sacc[56+sl2], f); }
}

// One block = one window-grid row (124 windows, iy = tid) of one image.
// Cooperative ballot-quantization of the 17 shared image rows into smem bitplanes.
__global__ void __launch_bounds__(128, 5) glcm_feat_kernel(const float* __restrict__ x,
                                                           float* __restrict__ out)
{
    __shared__ float sacc[68];
    __shared__ float slut[608];              // slut[s] = s*log2(s), s <= 578
    __shared__ uint32_t plane[17 * 4 * 17];  // [(r*4+l)*17 + w], w 0..15 data, 16 pad=0

    const int tid = threadIdx.x;
    const int b   = blockIdx.y;
    const int ix  = blockIdx.x;              // window-grid row, 0..123
    const float valid = (tid < 124) ? 1.0f : 0.0f;
    const int iy = (tid < 124) ? tid : 123;
    const bool lane0 = ((tid & 31) == 0);

    for (int i = tid; i < 68; i += 128) sacc[i] = 0.0f;
    for (int i = tid; i < 608; i += 128)
        slut[i] = (i == 0) ? 0.0f : (float)i * __log2f((float)i);
    for (int i = tid; i < 68; i += 128) plane[i * 17 + 16] = 0u;  // pad words

    const float B1 = 0.5f;
    const float B2 = (float)(85.384 - 53.798);
    const float B3 = 85.384f;
    const float B4 = (float)(85.384 + 53.798);

    const float* img = x + ((size_t)b << 18);
    const int row0 = ix * 4;

    // ---- cooperative quantization: 17 rows x 512 cols, ballot-packed ----
    {
        const int wrp  = tid >> 5;
        const int lane = tid & 31;
        #pragma unroll 1
        for (int g = wrp; g < 272; g += 4) {       // 272 = 17 rows * 16 col-words
            const int r  = g >> 4;
            const int kw = g & 15;
            const float pv = img[(row0 + r) * 512 + kw * 32 + lane];
            const uint32_t b1 = __ballot_sync(0xffffffffu, pv >= B1);
            const uint32_t b2 = __ballot_sync(0xffffffffu, pv >= B2);
            const uint32_t b3 = __ballot_sync(0xffffffffu, pv >= B3);
            const uint32_t b4 = __ballot_sync(0xffffffffu, pv >= B4);
            if (lane == 0) {
                plane[(r*4+0)*17 + kw] = b1;
                plane[(r*4+1)*17 + kw] = b2;
                plane[(r*4+2)*17 + kw] = b3;
                plane[(r*4+3)*17 + kw] = b4;
            }
        }
    }
    __syncthreads();

    // ---- per-window: stats pass + row-mask assembly into register bitmaps ----
    uint32_t C[4][12];
    #pragma unroll
    for (int j = 0; j < 4; ++j)
        #pragma unroll
        for (int w = 0; w < 12; ++w) C[j][w] = 0u;

    uint64_t sum2 = pkf2(0.0f, 0.0f);
    uint64_t sq2  = pkf2(0.0f, 0.0f);
    const uint64_t negMean2 = pkf2(-G_MEAN_F, -G_MEAN_F);
    float sumS = 0.f, sqS = 0.f, mxv = 0.f, mnv = 1e30f;

    const float* base = img + (size_t)row0 * 512 + (size_t)(iy * 4);
    const int aw0 = iy >> 3;            // plane word holding the window's bits
    const int ash = (iy & 7) * 4;       // bit shift within that word

    #pragma unroll
    for (int r = 0; r < 17; ++r) {
        // stats from gmem (L1-hot, coalesced-ish float4)
        const float* row = base + r * 512;
        const float4* p4 = (const float4*)row;
        float4 q0 = p4[0], q1 = p4[1], q2 = p4[2], q3 = p4[3];
        float px[16] = {q0.x,q0.y,q0.z,q0.w, q1.x,q1.y,q1.z,q1.w,
                        q2.x,q2.y,q2.z,q2.w, q3.x,q3.y,q3.z,q3.w};
        #pragma unroll
        for (int p = 0; p < 8; ++p) {
            uint64_t pk = pkf2(px[2*p], px[2*p+1]);
            sum2 = add_f32x2(sum2, pk);
            uint64_t d2 = add_f32x2(pk, negMean2);
            sq2 = fma_f32x2(d2, d2, sq2);
        }
        #pragma unroll
        for (int v = 0; v < 16; ++v) {
            mxv = fmaxf(mxv, px[v]);
            mnv = fminf(mnv, px[v]);
        }
        { // tail element 16
            float pv = row[16];
            sumS += pv;
            float d = pv - G_MEAN_F;
            sqS = fmaf(d, d, sqS);
            mxv = fmaxf(mxv, pv);
            mnv = fminf(mnv, pv);
        }

        // assemble 17-bit row masks from shared bitplanes (broadcast LDS)
        const uint32_t* pr = &plane[(r * 4) * 17];
        const uint32_t g1 = __funnelshift_r(pr[ 0 + aw0], pr[ 0 + aw0 + 1], ash) & 0x1FFFFu;
        const uint32_t g2 = __funnelshift_r(pr[17 + aw0], pr[17 + aw0 + 1], ash) & 0x1FFFFu;
        const uint32_t g3 = __funnelshift_r(pr[34 + aw0], pr[34 + aw0 + 1], ash) & 0x1FFFFu;
        const uint32_t g4 = __funnelshift_r(pr[51 + aw0], pr[51 + aw0 + 1], ash) & 0x1FFFFu;

        const int bp = r * 17;
        const int w0 = bp >> 5;
        const int sh = bp & 31;
        C[0][w0] |= g1 << sh;
        C[1][w0] |= g2 << sh;
        C[2][w0] |= g3 << sh;
        C[3][w0] |= g4 << sh;
        if (sh > 15) {
            C[0][w0+1] |= g1 >> (32 - sh);
            C[1][w0+1] |= g2 >> (32 - sh);
            C[2][w0+1] |= g3 >> (32 - sh);
            C[3][w0+1] |= g4 >> (32 - sh);
        }
    }

    // ---- stats + histogram channels (0..7) ----
    {
        float slo, shi, qlo, qhi;
        upk2(sum2, slo, shi);
        upk2(sq2,  qlo, qhi);
        float sum = sumS + slo + shi;
        float sq  = sqS + qlo + qhi;

        int P1=0,P2=0,P3=0,P4=0;
        #pragma unroll
        for (int w = 0; w < 10; ++w) {
            P1 += __popc(C[0][w]); P2 += __popc(C[1][w]);
            P3 += __popc(C[2][w]); P4 += __popc(C[3][w]);
        }
        int h1 = P1 - P2, h2 = P2 - P3, h3 = P3 - P4, h4 = P4;

        const float inv289 = 1.0f / 289.0f;
        float mean  = sum * inv289;
        float var0  = fmaxf(sq * inv289 - (mean - G_MEAN_F) * (mean - G_MEAN_F), 0.0f);
        float stdv  = sqrtf(var0);
        float mnorm = mean * (1.0f / G_MEAN_F);

        float f;
        f = warp_sum(mnorm * valid);                            if (lane0) atomicAdd(&sacc[0], f);
        f = warp_sum((stdv * (1.0f/G_STD_F)) * valid);          if (lane0) atomicAdd(&sacc[1], f);
        f = warp_sum(((mxv - mnorm) * (1.0f/G_STD_F)) * valid); if (lane0) atomicAdd(&sacc[2], f);
        f = warp_sum(((mnorm - mnv) * (1.0f/G_STD_F)) * valid); if (lane0) atomicAdd(&sacc[3], f);

        int toti = h1 + h2 + h3 + h4;
        float invt = (toti > 0) ? __fdividef(1.0f, (float)toti) : 0.0f;
        f = warp_sum((float)h1 * invt * valid);                 if (lane0) atomicAdd(&sacc[4], f);
        f = warp_sum((float)h2 * invt * valid);                 if (lane0) atomicAdd(&sacc[5], f);
        f = warp_sum((float)h3 * invt * valid);                 if (lane0) atomicAdd(&sacc[6], f);
        f = warp_sum((float)h4 * invt * valid);                 if (lane0) atomicAdd(&sacc[7], f);
    }

    // ---- GLCM: 4 compact bodies grouped by (WO, WMAX) ----
    float feat[5];

    #pragma unroll 1
    for (int o = 0; o < 3; ++o) {          // WO=0, dr=0: words 0..9
        do_off<0, 10>(OP[o], C, slut, feat);
        emit_feats(OP[o], feat, valid, sacc, lane0);
    }
    #pragma unroll 1
    for (int o = 3; o < 6; ++o) {          // WO=0, dr=1: words 0..8
        do_off<0, 9>(OP[o], C, slut, feat);
        emit_feats(OP[o], feat, valid, sacc, lane0);
    }
    #pragma unroll 1
    for (int o = 6; o < 9; ++o) {          // WO=1 (dr=2,3): words 0..7
        do_off<1, 8>(OP[o], C, slut, feat);
        emit_feats(OP[o], feat, valid, sacc, lane0);
    }
    {                                      // WO=2 (dr=4): words 0..6
        do_off<2, 7>(OP[9], C, slut, feat);
        emit_feats(OP[9], feat, valid, sacc, lane0);
    }

    __syncthreads();
    if (tid < 68) atomicAdd(&out[b * 68 + tid], sacc[tid] * (1.0f / 15376.0f));
}

extern "C" void kernel_launch(void* const* d_in, const int* in_sizes, int n_in,
                              void* d_out, int out_size) {
    const float* x = (const float*)d_in[0];
    float* out = (float*)d_out;
    cudaMemsetAsync(out, 0, (size_t)out_size * sizeof(float), 0);
    dim3 grid(124, 8);   // one window-grid row per block, y = batch
    glcm_feat_kernel<<<grid, 128>>>(x, out);
}

// round 17
// speedup vs baseline: 1.1382x; 1.1382x over previous
#include <cuda_runtime.h>
#include <stdint.h>

#define G_MEAN_F 85.384f
#define G_STD_F  53.798f

static __device__ __forceinline__ float warp_sum(float f) {
    #pragma unroll
    for (int o = 16; o; o >>= 1) f += __shfl_down_sync(0xffffffffu, f, o);
    return f;
}

// packed f32x2 helpers (sm_103a)
static __device__ __forceinline__ uint64_t pkf2(float lo, float hi) {
    uint64_t r; asm("mov.b64 %0, {%1, %2};" : "=l"(r) : "f"(lo), "f"(hi)); return r;
}
static __device__ __forceinline__ uint64_t add_f32x2(uint64_t a, uint64_t b) {
    uint64_t r; asm("add.rn.f32x2 %0, %1, %2;" : "=l"(r) : "l"(a), "l"(b)); return r;
}
static __device__ __forceinline__ uint64_t fma_f32x2(uint64_t a, uint64_t b, uint64_t c) {
    uint64_t r; asm("fma.rn.f32x2 %0, %1, %2, %3;" : "=l"(r) : "l"(a), "l"(b), "l"(c)); return r;
}
static __device__ __forceinline__ void upk2(uint64_t v, float& lo, float& hi) {
    asm("mov.b64 {%0, %1}, %2;" : "=f"(lo), "=f"(hi) : "l"(v));
}

// Per-offset parameters, built at compile time, stored in __constant__.
struct OffParams {
    uint32_t mask[10];  // 289-bit validity mask for 'a' positions (words 0..9)
    int      sh;        // K & 31  (K = dr*17+dc)
    int      tot;       // (17-dr)*(17-|dc|)
    float    invTot;    // 1 / (2*tot)
    int      slot1;     // output slot
    int      slot2;     // duplicate slot or -1
};

static constexpr OffParams make_op(int dr, int dc, int s1, int s2) {
    OffParams p{};
    const int adc = dc < 0 ? -dc : dc;
    for (int r = 0; r <= 16 - dr; ++r)
        for (int c = 0; c < 17; ++c) {
            bool ok = (dc >= 0) ? (c <= 16 - dc) : (c >= adc);
            if (ok) { int q = r * 17 + c; p.mask[q >> 5] |= (1u << (q & 31)); }
        }
    const int K = dr * 17 + dc;
    p.sh = K & 31;
    p.tot = (17 - dr) * (17 - adc);
    p.invTot = 1.0f / (2.0f * (float)p.tot);
    p.slot1 = s1;
    p.slot2 = s2;
    return p;
}

// Grouped by (word-offset WO, max nonzero mask word WMAX):
//  [0..2]  WO=0 WMAX=10 : (0,1) (0,2) (0,4)        [dr=0]
//  [3..5]  WO=0 WMAX=9  : (1,1) (1,-1) (1,0)       [dr=1]
//  [6..8]  WO=1 WMAX=8  : (2,0) (3,3) (3,-3)
//  [9]     WO=2 WMAX=7  : (4,0)
__constant__ OffParams OP[10] = {
    make_op(0, 1,  0, -1),
    make_op(0, 2,  4, -1),
    make_op(0, 4,  8, -1),
    make_op(1, 1,  1,  5),
    make_op(1,-1,  3,  7),
    make_op(1, 0,  2, -1),
    make_op(2, 0,  6, -1),
    make_op(3, 3,  9, -1),
    make_op(3,-3, 11, -1),
    make_op(4, 0, 10, -1),
};

// GLCM symmetric counting + features for one offset; WO compile-time (static reg
// indices into C), sh/mask/tot runtime from constant memory.
// Entropy uses smem LUT slut[s] = s*log2(s).
template<int WO, int WMAX>
__device__ __forceinline__ void do_off(const OffParams& op, const uint32_t C[4][12],
                                       const float* __restrict__ slut, float feat[5])
{
    const int sh = op.sh;

    int X12=0, X13=0, X14=0, X23=0, X24=0, X34=0;
    int D1=0, D2=0, D3=0, D4=0;
    int E1=0, E2=0, E3=0, E4=0;

    #pragma unroll
    for (int w = 0; w < WMAX; ++w) {
        const uint32_t mk = op.mask[w];
        const uint32_t a0 = C[0][w], a1 = C[1][w], a2 = C[2][w], a3 = C[3][w];
        const uint32_t s0 = __funnelshift_r(C[0][w+WO], C[0][w+WO+1], sh) & mk;
        const uint32_t s1 = __funnelshift_r(C[1][w+WO], C[1][w+WO+1], sh) & mk;
        const uint32_t s2 = __funnelshift_r(C[2][w+WO], C[2][w+WO+1], sh) & mk;
        const uint32_t s3 = __funnelshift_r(C[3][w+WO], C[3][w+WO+1], sh) & mk;

        E1 += __popc(a0 & mk) + __popc(s0);
        E2 += __popc(a1 & mk) + __popc(s1);
        E3 += __popc(a2 & mk) + __popc(s2);
        E4 += __popc(a3 & mk) + __popc(s3);

        D1 += __popc(a0 & s0);
        D2 += __popc(a1 & s1);
        D3 += __popc(a2 & s2);
        D4 += __popc(a3 & s3);

        X12 += __popc(a0 & s1) + __popc(a1 & s0);
        X13 += __popc(a0 & s2) + __popc(a2 & s0);
        X14 += __popc(a0 & s3) + __popc(a3 & s0);
        X23 += __popc(a1 & s2) + __popc(a2 & s1);
        X24 += __popc(a1 & s3) + __popc(a3 & s1);
        X34 += __popc(a2 & s3) + __popc(a3 & s2);
    }

    // symmetrized cells from symmetric cumulative scalars
    const int TOT = op.tot;
    const int U11 = 2*D1, U22 = 2*D2, U33 = 2*D3, U44 = 2*D4;
    const int s00 = 2*TOT - 2*E1 + U11;
    const int s01 = E1  - U11 - E2  + X12;
    const int s02 = E2  - X12 - E3  + X13;
    const int s03 = E3  - X13 - E4  + X14;
    const int s04 = E4  - X14;
    const int s11 = U11 - 2*X12 + U22;
    const int s12 = X12 - U22 - X13 + X23;
    const int s13 = X13 - X23 - X14 + X24;
    const int s14 = X14 - X24;
    const int s22 = U22 - 2*X23 + U33;
    const int s23 = X23 - U33 - X24 + X34;
    const int s24 = X24 - X34;
    const int s33 = U33 - 2*X34 + U44;
    const int s34 = X34 - U44;
    const int s44 = U44;

    const float invTot = op.invTot;

    // contrast
    {
        int ci = (s01 + s12 + s23 + s34) + 4*(s02 + s13 + s24) + 9*(s03 + s14) + 16*s04;
        feat[0] = 2.0f * invTot * (float)ci;
    }
    // homogeneity
    {
        float hoU = 0.5f*(float)(s01+s12+s23+s34)
                  + 0.2f*(float)(s02+s13+s24)
                  + 0.1f*(float)(s03+s14)
                  + (1.0f/17.0f)*(float)s04;
        feat[1] = invTot * ((float)(s00+s11+s22+s33+s44) + 2.0f*hoU);
    }
    // energy
    {
        int e2i = s00*s00 + s11*s11 + s22*s22 + s33*s33 + s44*s44
                + 2*(s01*s01 + s02*s02 + s03*s03 + s04*s04
                   + s12*s12 + s13*s13 + s14*s14
                   + s23*s23 + s24*s24 + s34*s34);
        feat[2] = invTot * sqrtf((float)e2i);
    }
    // correlation
    {
        int t1 = s01+s11+s12+s13+s14;
        int t2 = s02+s12+s22+s23+s24;
        int t3 = s03+s13+s23+s33+s34;
        int t4 = s04+s14+s24+s34+s44;
        float mu  = invTot * (float)(t1 + 2*t2 + 3*t3 + 4*t4);
        float e2m = invTot * (float)(t1 + 4*t2 + 9*t3 + 16*t4);
        float varm = e2m - mu * mu;
        int wij = s11 + 4*s22 + 9*s33 + 16*s44
                + 2*(2*s12 + 3*s13 + 4*s14 + 6*s23 + 8*s24 + 12*s34);
        float cov = invTot * (float)wij - mu * mu;
        feat[3] = (varm < 1e-15f) ? 1.0f : __fdividef(cov, fmaxf(varm, 1e-30f));
    }
    // entropy via LUT: slut[s] = s*log2(s); diag x1, off-diag x2
    {
        float S1 = slut[s00] + slut[s11] + slut[s22] + slut[s33] + slut[s44];
        float S2 = slut[s01] + slut[s02] + slut[s03] + slut[s04]
                 + slut[s12] + slut[s13] + slut[s14]
                 + slut[s23] + slut[s24] + slut[s34];
        feat[4] = -fmaf(invTot, fmaf(2.0f, S2, S1), __log2f(invTot));
    }
}

static __device__ __forceinline__ void emit_feats(const OffParams& op, const float feat[5],
                                                  float valid, float* sacc, bool lane0)
{
    const int sl1 = op.slot1;
    const int sl2 = op.slot2;
    float f;
    f = warp_sum(feat[0] * valid);
    if (lane0) { atomicAdd(&sacc[ 8+sl1], f); if (sl2 >= 0) atomicAdd(&sacc[ 8+sl2], f); }
    f = warp_sum(feat[1] * valid);
    if (lane0) { atomicAdd(&sacc[20+sl1], f); if (sl2 >= 0) atomicAdd(&sacc[20+sl2], f); }
    f = warp_sum(feat[2] * valid);
    if (lane0) { atomicAdd(&sacc[32+sl1], f); if (sl2 >= 0) atomicAdd(&sacc[32+sl2], f); }
    f = warp_sum(feat[3] * valid);
    if (lane0) { atomicAdd(&sacc[44+sl1], f); if (sl2 >= 0) atomicAdd(&sacc[44+sl2], f); }
    f = warp_sum(feat[4] * valid);
    if (lane0) { atomicAdd(&sacc[56+sl1], f); if (sl2 >= 0) atomicAdd(&sacc[56+sl2], f); }
}

// One block = one window-grid row (124 windows, iy = tid) of one image.
// Cooperative ballot-quantization of the 17 shared image rows into smem bitplanes.
// plane layout: [r][kw][level] -> one STS.128 per (r,kw), broadcast LDS on read.
__global__ void __launch_bounds__(128, 5) glcm_feat_kernel(const float* __restrict__ x,
                                                           float* __restrict__ out)
{
    __shared__ float sacc[68];
    __shared__ float slut[608];                       // slut[s] = s*log2(s), s <= 578
    __shared__ __align__(16) uint32_t plane[17*17*4]; // [(r*17+kw)*4 + l]; kw=16 pad=0

    const int tid = threadIdx.x;
    const int b   = blockIdx.y;
    const int ix  = blockIdx.x;              // window-grid row, 0..123
    const float valid = (tid < 124) ? 1.0f : 0.0f;
    const int iy = (tid < 124) ? tid : 123;
    const bool lane0 = ((tid & 31) == 0);

    for (int i = tid; i < 68; i += 128) sacc[i] = 0.0f;
    for (int i = tid; i < 608; i += 128)
        slut[i] = (i == 0) ? 0.0f : (float)i * __log2f((float)i);
    // zero the kw=16 pad words (r 0..16, l 0..3 -> 68 words)
    for (int i = tid; i < 68; i += 128) {
        int r = i >> 2, l = i & 3;
        plane[(r * 17 + 16) * 4 + l] = 0u;
    }

    const float B1 = 0.5f;
    const float B2 = (float)(85.384 - 53.798);
    const float B3 = 85.384f;
    const float B4 = (float)(85.384 + 53.798);

    const float* img = x + ((size_t)b << 18);
    const int row0 = ix * 4;

    // ---- cooperative quantization: 272 groups (17 rows x 16 col-words), 4 warps ----
    {
        const int wrp  = tid >> 5;
        const int lane = tid & 31;
        #pragma unroll 4
        for (int g = wrp; g < 272; g += 4) {
            const int r  = g >> 4;
            const int kw = g & 15;
            const float pv = img[(row0 + r) * 512 + kw * 32 + lane];
            const uint32_t b1 = __ballot_sync(0xffffffffu, pv >= B1);
            const uint32_t b2 = __ballot_sync(0xffffffffu, pv >= B2);
            const uint32_t b3 = __ballot_sync(0xffffffffu, pv >= B3);
            const uint32_t b4 = __ballot_sync(0xffffffffu, pv >= B4);
            if (lane == 0) {
                *reinterpret_cast<uint4*>(&plane[(r * 17 + kw) * 4]) =
                    make_uint4(b1, b2, b3, b4);
            }
        }
    }
    __syncthreads();

    // ---- per-window: stats pass + row-mask assembly into register bitmaps ----
    uint32_t C[4][12];
    #pragma unroll
    for (int j = 0; j < 4; ++j)
        #pragma unroll
        for (int w = 0; w < 12; ++w) C[j][w] = 0u;

    uint64_t sum2 = pkf2(0.0f, 0.0f);
    uint64_t sq2  = pkf2(0.0f, 0.0f);
    const uint64_t negMean2 = pkf2(-G_MEAN_F, -G_MEAN_F);
    float sumS = 0.f, sqS = 0.f, mxv = 0.f, mnv = 1e30f;

    const float* base = img + (size_t)row0 * 512 + (size_t)(iy * 4);
    const int aw0 = iy >> 3;            // plane col-word holding the window's bits
    const int ash = (iy & 7) * 4;       // bit shift within that word

    #pragma unroll
    for (int r = 0; r < 17; ++r) {
        // stats from gmem (L1-hot float4)
        const float* row = base + r * 512;
        const float4* p4 = (const float4*)row;
        float4 q0 = p4[0], q1 = p4[1], q2 = p4[2], q3 = p4[3];
        float px[16] = {q0.x,q0.y,q0.z,q0.w, q1.x,q1.y,q1.z,q1.w,
                        q2.x,q2.y,q2.z,q2.w, q3.x,q3.y,q3.z,q3.w};
        #pragma unroll
        for (int p = 0; p < 8; ++p) {
            uint64_t pk = pkf2(px[2*p], px[2*p+1]);
            sum2 = add_f32x2(sum2, pk);
            uint64_t d2 = add_f32x2(pk, negMean2);
            sq2 = fma_f32x2(d2, d2, sq2);
        }
        #pragma unroll
        for (int v = 0; v < 16; ++v) {
            mxv = fmaxf(mxv, px[v]);
            mnv = fminf(mnv, px[v]);
        }
        { // tail element 16
            float pv = row[16];
            sumS += pv;
            float d = pv - G_MEAN_F;
            sqS = fmaf(d, d, sqS);
            mxv = fmaxf(mxv, pv);
            mnv = fminf(mnv, pv);
        }

        // assemble 17-bit row masks from shared bitplanes (broadcast LDS, 2x uint4)
        const uint4 w0v = *reinterpret_cast<const uint4*>(&plane[(r * 17 + aw0) * 4]);
        const uint4 w1v = *reinterpret_cast<const uint4*>(&plane[(r * 17 + aw0 + 1) * 4]);
        const uint32_t g1 = __funnelshift_r(w0v.x, w1v.x, ash) & 0x1FFFFu;
        const uint32_t g2 = __funnelshift_r(w0v.y, w1v.y, ash) & 0x1FFFFu;
        const uint32_t g3 = __funnelshift_r(w0v.z, w1v.z, ash) & 0x1FFFFu;
        const uint32_t g4 = __funnelshift_r(w0v.w, w1v.w, ash) & 0x1FFFFu;

        const int bp = r * 17;
        const int w0 = bp >> 5;
        const int sh = bp & 31;
        C[0][w0] |= g1 << sh;
        C[1][w0] |= g2 << sh;
        C[2][w0] |= g3 << sh;
        C[3][w0] |= g4 << sh;
        if (sh > 15) {
            C[0][w0+1] |= g1 >> (32 - sh);
            C[1][w0+1] |= g2 >> (32 - sh);
            C[2][w0+1] |= g3 >> (32 - sh);
            C[3][w0+1] |= g4 >> (32 - sh);
        }
    }

    // ---- stats + histogram channels (0..7) ----
    {
        float slo, shi, qlo, qhi;
        upk2(sum2, slo, shi);
        upk2(sq2,  qlo, qhi);
        float sum = sumS + slo + shi;
        float sq  = sqS + qlo + qhi;

        int P1=0,P2=0,P3=0,P4=0;
        #pragma unroll
        for (int w = 0; w < 10; ++w) {
            P1 += __popc(C[0][w]); P2 += __popc(C[1][w]);
            P3 += __popc(C[2][w]); P4 += __popc(C[3][w]);
        }
        int h1 = P1 - P2, h2 = P2 - P3, h3 = P3 - P4, h4 = P4;

        const float inv289 = 1.0f / 289.0f;
        float mean  = sum * inv289;
        float var0  = fmaxf(sq * inv289 - (mean - G_MEAN_F) * (mean - G_MEAN_F), 0.0f);
        float stdv  = sqrtf(var0);
        float mnorm = mean * (1.0f / G_MEAN_F);

        float f;
        f = warp_sum(mnorm * valid);                            if (lane0) atomicAdd(&sacc[0], f);
        f = warp_sum((stdv * (1.0f/G_STD_F)) * valid);          if (lane0) atomicAdd(&sacc[1], f);
        f = warp_sum(((mxv - mnorm) * (1.0f/G_STD_F)) * valid); if (lane0) atomicAdd(&sacc[2], f);
        f = warp_sum(((mnorm - mnv) * (1.0f/G_STD_F)) * valid); if (lane0) atomicAdd(&sacc[3], f);

        int toti = h1 + h2 + h3 + h4;
        float invt = (toti > 0) ? __fdividef(1.0f, (float)toti) : 0.0f;
        f = warp_sum((float)h1 * invt * valid);                 if (lane0) atomicAdd(&sacc[4], f);
        f = warp_sum((float)h2 * invt * valid);                 if (lane0) atomicAdd(&sacc[5], f);
        f = warp_sum((float)h3 * invt * valid);                 if (lane0) atomicAdd(&sacc[6], f);
        f = warp_sum((float)h4 * invt * valid);                 if (lane0) atomicAdd(&sacc[7], f);
    }

    // ---- GLCM: 4 compact bodies grouped by (WO, WMAX) ----
    float feat[5];

    #pragma unroll 1
    for (int o = 0; o < 3; ++o) {          // WO=0, dr=0: words 0..9
        do_off<0, 10>(OP[o], C, slut, feat);
        emit_feats(OP[o], feat, valid, sacc, lane0);
    }
    #pragma unroll 1
    for (int o = 3; o < 6; ++o) {          // WO=0, dr=1: words 0..8
        do_off<0, 9>(OP[o], C, slut, feat);
        emit_feats(OP[o], feat, valid, sacc, lane0);
    }
    #pragma unroll 1
    for (int o = 6; o < 9; ++o) {          // WO=1 (dr=2,3): words 0..7
        do_off<1, 8>(OP[o], C, slut, feat);
        emit_feats(OP[o], feat, valid, sacc, lane0);
    }
    {                                      // WO=2 (dr=4): words 0..6
        do_off<2, 7>(OP[9], C, slut, feat);
        emit_feats(OP[9], feat, valid, sacc, lane0);
    }

    __syncthreads();
    if (tid < 68) atomicAdd(&out[b * 68 + tid], sacc[tid] * (1.0f / 15376.0f));
}

extern "C" void kernel_launch(void* const* d_in, const int* in_sizes, int n_in,
                              void* d_out, int out_size) {
    const float* x = (const float*)d_in[0];
    float* out = (float*)d_out;
    cudaMemsetAsync(out, 0, (size_t)out_size * sizeof(float), 0);
    dim3 grid(124, 8);   // one window-grid row per block, y = batch
    glcm_feat_kernel<<<grid, 128>>>(x, out);
}